// round 1
// baseline (speedup 1.0000x reference)
#include <cuda_runtime.h>

#define D_   768
#define NH_  12
#define P_   5
#define NL_  54
#define NS_  256
#define B_   128
#define NTL_ 49           // NL_ - P_
#define ML_  (B_*NL_)     // 6912
#define MS_  (B_*NS_)     // 32768

// ---------------- scratch (device globals; no allocation in kernel_launch) ----------------
__device__ float g_local[(size_t)ML_*D_];
__device__ float g_scene[(size_t)MS_*D_];
__device__ float g_q    [(size_t)MS_*D_];
__device__ float g_k    [(size_t)MS_*D_];
__device__ float g_v    [(size_t)MS_*D_];
__device__ float g_ao   [(size_t)MS_*D_];
__device__ float g_h    [(size_t)ML_*D_];
__device__ float g_qkv  [(size_t)ML_*3*D_];
__device__ float g_mlp  [(size_t)ML_*4*D_];
__device__ float g_lsin [B_*NTL_*32];
__device__ float g_lcos [B_*NTL_*32];
__device__ float g_ssin [NS_*32];
__device__ float g_scos [NS_*32];

__device__ __forceinline__ float gelu_f(float x){
    float t = tanhf(0.7978845608028654f*(x + 0.044715f*x*x*x));
    return 0.5f*x*(1.0f+t);
}

// ---------------- SGEMM: C(MxN) = A(MxK) @ B(KxN), all row-major, dims divisible by tile ----
// EPI: 0 = store, 1 = gelu(acc), 2 = C += acc, 3 = C += gate[col]*acc
template<int EPI>
__global__ __launch_bounds__(256) void sgemm(const float* __restrict__ A,
                                             const float* __restrict__ Bm,
                                             float* __restrict__ C,
                                             const float* __restrict__ gate,
                                             int M, int N, int K)
{
    __shared__ float As[16][64];
    __shared__ float Bs[16][64];
    const int tid = threadIdx.x;
    const int bx = blockIdx.x, by = blockIdx.y;
    const float* Ab = A  + (size_t)by*64*K;
    const float* Bb = Bm + (size_t)bx*64;
    const int ar = tid >> 2,  ac = (tid & 3)  << 2;   // A load: 64 rows x 16 cols
    const int br = tid >> 4,  bc = (tid & 15) << 2;   // B load: 16 rows x 64 cols
    const int ty = tid >> 4,  tx = tid & 15;

    float acc[4][4];
    #pragma unroll
    for (int i=0;i<4;i++)
        #pragma unroll
        for (int j=0;j<4;j++) acc[i][j]=0.f;

    for (int k0 = 0; k0 < K; k0 += 16) {
        float4 a4 = *reinterpret_cast<const float4*>(Ab + (size_t)ar*K + k0 + ac);
        As[ac+0][ar]=a4.x; As[ac+1][ar]=a4.y; As[ac+2][ar]=a4.z; As[ac+3][ar]=a4.w;
        float4 b4 = *reinterpret_cast<const float4*>(Bb + (size_t)(k0+br)*N + bc);
        *reinterpret_cast<float4*>(&Bs[br][bc]) = b4;
        __syncthreads();
        #pragma unroll
        for (int kk=0;kk<16;kk++){
            float a0[4], b0[4];
            #pragma unroll
            for (int i=0;i<4;i++) a0[i]=As[kk][(ty<<2)+i];
            #pragma unroll
            for (int j=0;j<4;j++) b0[j]=Bs[kk][(tx<<2)+j];
            #pragma unroll
            for (int i=0;i<4;i++)
                #pragma unroll
                for (int j=0;j<4;j++) acc[i][j] += a0[i]*b0[j];
        }
        __syncthreads();
    }

    const int row0 = by*64 + (ty<<2);
    const int col0 = bx*64 + (tx<<2);
    #pragma unroll
    for (int i=0;i<4;i++){
        float* cp = C + (size_t)(row0+i)*N + col0;
        #pragma unroll
        for (int j=0;j<4;j++){
            float vv = acc[i][j];
            if      (EPI==0) cp[j] = vv;
            else if (EPI==1) cp[j] = gelu_f(vv);
            else if (EPI==2) cp[j] += vv;
            else             cp[j] += gate[col0+j]*vv;
        }
    }
}

// ---------------- LayerNorm over D=768, one block per row ----------------
__global__ __launch_bounds__(256) void layernorm_k(const float* __restrict__ X,
                                                   float* __restrict__ Y,
                                                   const float* __restrict__ g,
                                                   const float* __restrict__ bb)
{
    __shared__ float red[256];
    const int row = blockIdx.x, tid = threadIdx.x;
    const float* x = X + (size_t)row*D_;
    float v0=x[tid], v1=x[tid+256], v2=x[tid+512];
    red[tid]=v0+v1+v2; __syncthreads();
    for (int o=128;o>0;o>>=1){ if(tid<o) red[tid]+=red[tid+o]; __syncthreads(); }
    float mean = red[0]*(1.f/768.f);
    __syncthreads();
    float d0=v0-mean, d1=v1-mean, d2=v2-mean;
    red[tid]=d0*d0+d1*d1+d2*d2; __syncthreads();
    for (int o=128;o>0;o>>=1){ if(tid<o) red[tid]+=red[tid+o]; __syncthreads(); }
    float inv = rsqrtf(red[0]*(1.f/768.f)+1e-6f);
    float* y = Y + (size_t)row*D_;
    y[tid]     = d0*inv*g[tid]     + bb[tid];
    y[tid+256] = d1*inv*g[tid+256] + bb[tid+256];
    y[tid+512] = d2*inv*g[tid+512] + bb[tid+512];
}

// ---------------- RoPE tables ----------------
__global__ void rope_local_pre(const float* __restrict__ centers, const float* __restrict__ scales){
    int t = blockIdx.x, b = blockIdx.y, j = threadIdx.x;   // grid (49, B), block 32
    int iy = t/7, ix = t%7;
    float gy = (iy+0.5f)*(2.f/7.f)-1.f;
    float gx = (ix+0.5f)*(2.f/7.f)-1.f;
    float sc = scales[b];
    float pos = (j<16) ? (centers[2*b]+sc*gy) : (centers[2*b+1]+sc*gx);
    float f = expf(-4.605170185988091f * (float)(j&15) * (1.f/16.f));  // 100^(-(j%16)/16)
    float a = pos*f;
    int idx = (b*NTL_+t)*32 + j;
    g_lsin[idx]=sinf(a); g_lcos[idx]=cosf(a);
}
__global__ void rope_scene_pre(){
    int t = blockIdx.x, j = threadIdx.x;                   // grid 256, block 32
    int iy = t/16, ix = t%16;
    float gy = (iy+0.5f)*(2.f/16.f)-1.f;
    float gx = (ix+0.5f)*(2.f/16.f)-1.f;
    float pos = (j<16)? gy : gx;
    float f = expf(-4.605170185988091f * (float)(j&15) * (1.f/16.f));
    float a = pos*f;
    g_ssin[t*32+j]=sinf(a); g_scos[t*32+j]=cosf(a);
}

// In-place rope on head-layout buffer. grid (N-prefix, B), block (32, NH)
__global__ void rope_apply(float* __restrict__ X, const float* __restrict__ S,
                           const float* __restrict__ C, int N, int prefix, int rs, int bi)
{
    int t = blockIdx.x, b = blockIdx.y;
    int j = threadIdx.x, h = threadIdx.y;
    int nt = gridDim.x;
    size_t so = bi ? ((size_t)t*32+j) : (((size_t)b*nt+t)*32+j);
    float s = S[so], c = C[so];
    float* xp = X + ((size_t)(b*N+prefix+t)*rs + h*64);
    float x1 = xp[j], x2 = xp[j+32];
    xp[j]    = x1*c - x2*s;
    xp[j+32] = x2*c + x1*s;
}

// ---------------- fused attention: block = (b, h, 64-query tile) ----------------
// smem: qt[64*65] | kv[64*65] | sc[64*Nk(max 256)]
__global__ __launch_bounds__(256) void attn_fused(const float* __restrict__ Q,
                                                  const float* __restrict__ K,
                                                  const float* __restrict__ V,
                                                  float* __restrict__ O,
                                                  int Nq, int Nk, int qs, int ks)
{
    extern __shared__ float sm[];
    float* qt = sm;
    float* kv = sm + 64*65;
    float* sc = sm + 2*64*65;
    const int q0 = blockIdx.x*64;
    const int h = blockIdx.y, b = blockIdx.z, tid = threadIdx.x;
    const int nq = min(64, Nq - q0);

    for (int u = tid; u < nq*16; u += 256) {
        int r = u >> 4, c4 = (u & 15) << 2;
        float4 v4 = *reinterpret_cast<const float4*>(Q + ((size_t)(b*Nq + q0 + r)*qs + h*64 + c4));
        qt[r*65+c4]=v4.x; qt[r*65+c4+1]=v4.y; qt[r*65+c4+2]=v4.z; qt[r*65+c4+3]=v4.w;
    }
    const int tq  = tid >> 2;      // query in tile
    const int tk0 = tid & 3;

    // QK^T * scale
    for (int c0 = 0; c0 < Nk; c0 += 64) {
        int nc = min(64, Nk - c0);
        __syncthreads();
        for (int u = tid; u < nc*16; u += 256) {
            int r = u >> 4, c4 = (u & 15) << 2;
            float4 v4 = *reinterpret_cast<const float4*>(K + ((size_t)(b*Nk + c0 + r)*ks + h*64 + c4));
            kv[r*65+c4]=v4.x; kv[r*65+c4+1]=v4.y; kv[r*65+c4+2]=v4.z; kv[r*65+c4+3]=v4.w;
        }
        __syncthreads();
        if (tq < nq) {
            #pragma unroll 4
            for (int m = 0; m < 16; m++) {
                int k = tk0 + (m<<2);
                if (k < nc) {
                    float d = 0.f;
                    #pragma unroll
                    for (int i = 0; i < 64; i++) d += qt[tq*65+i]*kv[k*65+i];
                    sc[tq*Nk + c0 + k] = d * 0.125f;
                }
            }
        }
    }
    __syncthreads();

    // softmax per row
    if (tid < nq) {
        float m = -1e30f;
        for (int k=0;k<Nk;k++) m = fmaxf(m, sc[tid*Nk+k]);
        float ssum = 0.f;
        for (int k=0;k<Nk;k++){ float e=expf(sc[tid*Nk+k]-m); sc[tid*Nk+k]=e; ssum+=e; }
        float inv = 1.f/ssum;
        for (int k=0;k<Nk;k++) sc[tid*Nk+k]*=inv;
    }
    __syncthreads();

    // P @ V
    const int dg = (tid & 3) << 4;
    float acc[16];
    #pragma unroll
    for (int j=0;j<16;j++) acc[j]=0.f;
    for (int c0 = 0; c0 < Nk; c0 += 64) {
        int nc = min(64, Nk - c0);
        __syncthreads();
        for (int u = tid; u < nc*16; u += 256) {
            int r = u >> 4, c4 = (u & 15) << 2;
            float4 v4 = *reinterpret_cast<const float4*>(V + ((size_t)(b*Nk + c0 + r)*ks + h*64 + c4));
            kv[r*65+c4]=v4.x; kv[r*65+c4+1]=v4.y; kv[r*65+c4+2]=v4.z; kv[r*65+c4+3]=v4.w;
        }
        __syncthreads();
        if (tq < nq) {
            for (int k=0;k<nc;k++){
                float p = sc[tq*Nk + c0 + k];
                #pragma unroll
                for (int j=0;j<16;j++) acc[j] += p*kv[k*65 + dg + j];
            }
        }
    }
    if (tq < nq) {
        float* op = O + ((size_t)(b*Nq + q0 + tq)*D_ + h*64 + dg);
        #pragma unroll
        for (int j=0;j<16;j++) op[j]=acc[j];
    }
}

// ---------------- init: broadcast scene tokens ----------------
__global__ void bcast_scene(const float* __restrict__ st){
    int off = blockIdx.x*256 + threadIdx.x;                // grid (NS_*D_/256, B_)
    g_scene[(size_t)blockIdx.y*(NS_*D_) + off] = st[off];
}

// ---------------- host ----------------
extern "C" void kernel_launch(void* const* d_in, const int* in_sizes, int n_in,
                              void* d_out, int out_size)
{
    (void)in_sizes; (void)n_in; (void)out_size;
    const float* in_local   = (const float*)d_in[0];
    const float* in_centers = (const float*)d_in[1];
    const float* in_scales  = (const float*)d_in[2];
    const float* in_scene   = (const float*)d_in[3];
    const float* rgate = (const float*)d_in[4];
    const float* wgate = (const float*)d_in[5];
    const float* rWq = (const float*)d_in[6];
    const float* rWk = (const float*)d_in[7];
    const float* rWv = (const float*)d_in[8];
    const float* rWo = (const float*)d_in[9];
    const float* wWq = (const float*)d_in[10];
    const float* wWk = (const float*)d_in[11];
    const float* wWv = (const float*)d_in[12];
    const float* wWo = (const float*)d_in[13];
    const float* ln1g = (const float*)d_in[14];
    const float* ln1b = (const float*)d_in[15];
    const float* qkvW = (const float*)d_in[16];
    const float* aWo  = (const float*)d_in[17];
    const float* ln2g = (const float*)d_in[18];
    const float* ln2b = (const float*)d_in[19];
    const float* mW1  = (const float*)d_in[20];
    const float* mW2  = (const float*)d_in[21];

    float *local,*scene,*q,*k,*v,*ao,*hb,*qkv,*mlp,*lsin,*lcos,*ssin,*scos;
    cudaGetSymbolAddress((void**)&local, g_local);
    cudaGetSymbolAddress((void**)&scene, g_scene);
    cudaGetSymbolAddress((void**)&q,   g_q);
    cudaGetSymbolAddress((void**)&k,   g_k);
    cudaGetSymbolAddress((void**)&v,   g_v);
    cudaGetSymbolAddress((void**)&ao,  g_ao);
    cudaGetSymbolAddress((void**)&hb,  g_h);
    cudaGetSymbolAddress((void**)&qkv, g_qkv);
    cudaGetSymbolAddress((void**)&mlp, g_mlp);
    cudaGetSymbolAddress((void**)&lsin, g_lsin);
    cudaGetSymbolAddress((void**)&lcos, g_lcos);
    cudaGetSymbolAddress((void**)&ssin, g_ssin);
    cudaGetSymbolAddress((void**)&scos, g_scos);

    const size_t smem_attn = (size_t)(2*64*65 + 64*256)*sizeof(float);   // ~98.8 KB
    cudaFuncSetAttribute(attn_fused, cudaFuncAttributeMaxDynamicSharedMemorySize, (int)smem_attn);

    cudaMemcpyAsync(local, in_local, sizeof(float)*(size_t)ML_*D_, cudaMemcpyDeviceToDevice);
    bcast_scene<<<dim3(NS_*D_/256, B_),256>>>(in_scene);
    rope_local_pre<<<dim3(NTL_,B_),32>>>(in_centers, in_scales);
    rope_scene_pre<<<NS_,32>>>();

    for (int i=0;i<12;i++){
        size_t wo = (size_t)i*D_*D_;
        // ---- READ cross-attn: q from local, kv from scene ----
        sgemm<0><<<dim3(12,108),256>>>(local, rWq+wo, q, nullptr, ML_, D_, D_);
        rope_apply<<<dim3(NTL_,B_),dim3(32,NH_)>>>(q, lsin, lcos, NL_, P_, D_, 0);
        sgemm<0><<<dim3(12,512),256>>>(scene, rWk+wo, k, nullptr, MS_, D_, D_);
        rope_apply<<<dim3(NS_,B_),dim3(32,NH_)>>>(k, ssin, scos, NS_, 0, D_, 1);
        sgemm<0><<<dim3(12,512),256>>>(scene, rWv+wo, v, nullptr, MS_, D_, D_);
        attn_fused<<<dim3(1,NH_,B_),256,smem_attn>>>(q,k,v,ao, NL_, NS_, D_, D_);
        sgemm<3><<<dim3(12,108),256>>>(ao, rWo+wo, local, rgate+(size_t)i*D_, ML_, D_, D_);

        // ---- ViT block on local ----
        layernorm_k<<<ML_,256>>>(local, hb, ln1g+(size_t)i*D_, ln1b+(size_t)i*D_);
        sgemm<0><<<dim3(36,108),256>>>(hb, qkvW+(size_t)i*D_*3*D_, qkv, nullptr, ML_, 3*D_, D_);
        rope_apply<<<dim3(NTL_,B_),dim3(32,NH_)>>>(qkv,     lsin, lcos, NL_, P_, 3*D_, 0);
        rope_apply<<<dim3(NTL_,B_),dim3(32,NH_)>>>(qkv+D_,  lsin, lcos, NL_, P_, 3*D_, 0);
        attn_fused<<<dim3(1,NH_,B_),256,smem_attn>>>(qkv, qkv+D_, qkv+2*D_, ao, NL_, NL_, 3*D_, 3*D_);
        sgemm<2><<<dim3(12,108),256>>>(ao, aWo+wo, local, nullptr, ML_, D_, D_);
        layernorm_k<<<ML_,256>>>(local, hb, ln2g+(size_t)i*D_, ln2b+(size_t)i*D_);
        sgemm<1><<<dim3(48,108),256>>>(hb, mW1+(size_t)i*D_*4*D_, mlp, nullptr, ML_, 4*D_, D_);
        sgemm<2><<<dim3(12,108),256>>>(mlp, mW2+(size_t)i*4*D_*D_, local, nullptr, ML_, D_, 4*D_);

        // ---- WRITE cross-attn: q from scene, kv from local ----
        sgemm<0><<<dim3(12,512),256>>>(scene, wWq+wo, q, nullptr, MS_, D_, D_);
        rope_apply<<<dim3(NS_,B_),dim3(32,NH_)>>>(q, ssin, scos, NS_, 0, D_, 1);
        sgemm<0><<<dim3(12,108),256>>>(local, wWk+wo, k, nullptr, ML_, D_, D_);
        rope_apply<<<dim3(NTL_,B_),dim3(32,NH_)>>>(k, lsin, lcos, NL_, P_, D_, 0);
        sgemm<0><<<dim3(12,108),256>>>(local, wWv+wo, v, nullptr, ML_, D_, D_);
        attn_fused<<<dim3(4,NH_,B_),256,smem_attn>>>(q,k,v,ao, NS_, NL_, D_, D_);
        sgemm<3><<<dim3(12,512),256>>>(ao, wWo+wo, scene, wgate+(size_t)i*D_, MS_, D_, D_);
    }

    cudaMemcpyAsync(d_out, local, sizeof(float)*(size_t)ML_*D_, cudaMemcpyDeviceToDevice);
    cudaMemcpyAsync((float*)d_out + (size_t)ML_*D_, scene, sizeof(float)*(size_t)MS_*D_,
                    cudaMemcpyDeviceToDevice);
}